// round 12
// baseline (speedup 1.0000x reference)
#include <cuda_runtime.h>
#include <math.h>

#define RE_D   6378.137
#define MU_D   398600.5
#define TWOPI_F 6.28318530717958647692f
#define INV_TWOPI_F 0.15915494309189533577f

#define XKE_F   ((float)(60.0 / sqrt(RE_D * RE_D * RE_D / MU_D)))
#define XKEI_F  ((float)(sqrt(RE_D * RE_D * RE_D / MU_D) / 60.0))
#define RE_F    ((float)RE_D)
#define J2_F    0.00108262998905f
#define J4_F    (-0.00000161098761f)
#define J3OJ2_F ((float)(-0.00000253215306 / 0.00108262998905))
#define X2O3_F  ((float)(2.0 / 3.0))
#define SS_F    ((float)(78.0 / RE_D + 1.0))
#define QZMS2T_F ((float)(((120.0 - 78.0) / RE_D) * ((120.0 - 78.0) / RE_D) \
                        * ((120.0 - 78.0) / RE_D) * ((120.0 - 78.0) / RE_D)))
#define VKPS_F  ((float)(RE_D * (60.0 / sqrt(RE_D * RE_D * RE_D / MU_D)) / 60.0))

// ---------------- packed f32x2 ----------------
struct pf { unsigned long long v; };

__device__ __forceinline__ pf pk(float x, float y) {
    pf r; asm("mov.b64 %0,{%1,%2};" : "=l"(r.v) : "f"(x), "f"(y)); return r;
}
__device__ __forceinline__ float2 up(pf a) {
    float2 r; asm("mov.b64 {%0,%1},%2;" : "=f"(r.x), "=f"(r.y) : "l"(a.v)); return r;
}
__device__ __forceinline__ pf ps(float s) { return pk(s, s); }

__device__ __forceinline__ pf operator+(pf a, pf b) {
    pf r; asm("add.rn.f32x2 %0,%1,%2;" : "=l"(r.v) : "l"(a.v), "l"(b.v)); return r;
}
__device__ __forceinline__ pf operator*(pf a, pf b) {
    pf r; asm("mul.rn.f32x2 %0,%1,%2;" : "=l"(r.v) : "l"(a.v), "l"(b.v)); return r;
}
__device__ __forceinline__ pf pfma(pf a, pf b, pf c) {
    pf r; asm("fma.rn.f32x2 %0,%1,%2,%3;" : "=l"(r.v) : "l"(a.v), "l"(b.v), "l"(c.v)); return r;
}
__device__ __forceinline__ pf operator-(pf a, pf b) { return pfma(b, ps(-1.0f), a); }
__device__ __forceinline__ pf pneg(pf a) { return a * ps(-1.0f); }

__device__ __forceinline__ float frcp(float x) { float r; asm("rcp.approx.f32 %0,%1;" : "=f"(r) : "f"(x)); return r; }
__device__ __forceinline__ float fsqa(float x) { float r; asm("sqrt.approx.f32 %0,%1;" : "=f"(r) : "f"(x)); return r; }
__device__ __forceinline__ float frsq(float x) { float r; asm("rsqrt.approx.f32 %0,%1;" : "=f"(r) : "f"(x)); return r; }

__device__ __forceinline__ pf prcp(pf a)  { float2 t = up(a); return pk(frcp(t.x), frcp(t.y)); }
__device__ __forceinline__ pf pdiv(pf a, pf b) { return a * prcp(b); }
__device__ __forceinline__ pf psqrt(pf a) { float2 t = up(a); return pk(fsqa(t.x), fsqa(t.y)); }
__device__ __forceinline__ pf prsqrt(pf a){ float2 t = up(a); return pk(frsq(t.x), frsq(t.y)); }
__device__ __forceinline__ pf pfloor(pf a){ float2 t = up(a); return pk(floorf(t.x), floorf(t.y)); }
__device__ __forceinline__ pf pcos(pf a)  { float2 t = up(a); return pk(__cosf(t.x), __cosf(t.y)); }
__device__ __forceinline__ void psc(pf a, pf& s, pf& c) {
    float2 t = up(a); float s0, c0, s1, c1;
    __sincosf(t.x, &s0, &c0); __sincosf(t.y, &s1, &c1);
    s = pk(s0, s1); c = pk(c0, c1);
}
__device__ __forceinline__ pf pmod2pi(pf x) {
    pf q = pfloor(x * ps(INV_TWOPI_F));
    return pfma(q, ps(-TWOPI_F), x);
}

// Inclination trig: hybrid accurate/fast (R2 post-mortem). Accurate path only
// where 1+cosio cancellation (divided into xlcof) is comparable to trig noise.
__device__ __forceinline__ void incl_trig(float inclo, float& s, float& c, float& d) {
    if (inclo > 3.1296f) {
        sincosf(inclo, &s, &c);
        float dd = 1.0f + c;
        d = (fabsf(dd) > 1.5e-12f) ? dd : 1.5e-12f;
    } else {
        __sincosf(inclo, &s, &c);
        d = 1.0f + c;
    }
}

// Specialization (R6/R9): input support -> isimp=false, sfour=SS,
// qzms24=QZMS2T, ecco>1e-4, eeta>3e-6; cc1<=2.9e-11 kills d2..d4,
// t3cof..t5cof, nodecf below f32 rounding; |per|<=6.5e-5; em>0 (clamp dead).

// One packed pair of satellites: params pa[7] (sat A), pb[7] (sat B).
__device__ __forceinline__ void sgp4_core(
    const float* __restrict__ pa, const float* __restrict__ pb,
    float t0v, float t1v,
    pf& PX, pf& PY, pf& PZ, pf& VX, pf& VY, pf& VZ)
{
    pf ecco  = pk(pa[1], pb[1]);
    pf inclo = pk(pa[2], pb[2]);
    pf bstar = pk(pa[6], pb[6]);
    pf t     = pk(t0v, t1v);
    pf t2 = t * t;

    pf omeosq = ps(1.0f) - ecco * ecco;
    pf rteosq = psqrt(omeosq);

    float si0, ci0, dn0, si1, ci1, dn1;
    incl_trig(pa[2], si0, ci0, dn0);
    incl_trig(pb[2], si1, ci1, dn1);
    pf sinio = pk(si0, si1);
    pf cosio = pk(ci0, ci1);
    pf denom = pk(dn0, dn1);
    pf cosio2 = cosio * cosio;

    float ak0 = __powf(__fdividef(XKE_F, pa[0]), X2O3_F);
    float ak1 = __powf(__fdividef(XKE_F, pb[0]), X2O3_F);
    pf ak = pk(ak0, ak1);
    pf n_koz = pk(pa[0], pb[0]);

    pf d1   = pdiv(ps(0.75f * J2_F) * pfma(ps(3.0f), cosio2, ps(-1.0f)), rteosq * omeosq);
    pf del1 = pdiv(d1, ak * ak);
    pf dl1sq = del1 * del1;
    pf adel = ak * (ps(1.0f) - dl1sq - del1 * pfma(dl1sq, ps(134.0f / 81.0f), ps(1.0f / 3.0f)));
    pf del_ = pdiv(d1, adel * adel);
    pf no_unk = pdiv(n_koz, ps(1.0f) + del_);
    pf dsq = del_ * del_;
    pf ao = ak * (ps(1.0f) + ps(X2O3_F) * del_ + ps(-1.0f / 9.0f) * dsq
                + ps(4.0f / 81.0f) * (dsq * del_));

    pf po    = ao * omeosq;
    pf con42 = pfma(ps(-5.0f), cosio2, ps(1.0f));
    pf con41 = pfma(ps(-2.0f), cosio2, pneg(con42));
    pf pinvsq = prcp(po * po);
    pf tsi    = prcp(ao - ps(SS_F));
    pf eta    = ao * ecco * tsi;
    pf etasq  = eta * eta;
    pf eeta   = ecco * eta;
    pf psisq  = ps(1.0f) - etasq;
    pf rs     = prsqrt(psisq);
    pf rpsi   = rs * rs;
    pf rao    = prcp(ao);
    pf tsi2   = tsi * tsi;
    pf coef   = ps(QZMS2T_F) * (tsi2 * tsi2);
    pf coef1  = coef * (rpsi * rpsi) * (rpsi * rs);
    pf x1mth2 = ps(1.0f) - cosio2;
    pf cosio4 = cosio2 * cosio2;

    pf jtsips = ps(J2_F) * tsi * rpsi;
    pf cc2 = coef1 * no_unk * (ao * (ps(1.0f) + ps(1.5f) * etasq + eeta * (ps(4.0f) + etasq))
           + ps(0.375f) * jtsips * con41 * (ps(8.0f) + ps(3.0f) * etasq * (ps(8.0f) + etasq)));
    pf cc1 = bstar * cc2;

    pf temp1 = ps(1.5f * J2_F) * pinvsq * no_unk;
    pf temp2 = ps(0.5f) * temp1 * ps(J2_F) * pinvsq;
    pf temp3 = ps(-0.46875f * J4_F) * pinvsq * pinvsq * no_unk;
    pf mdot = no_unk + ps(0.5f) * temp1 * rteosq * con41
            + ps(0.0625f) * temp2 * rteosq *
              (ps(13.0f) + ps(-78.0f) * cosio2 + ps(137.0f) * cosio4);
    pf argpdot = ps(-0.5f) * temp1 * con42
               + ps(0.0625f) * temp2 * (ps(7.0f) + ps(-114.0f) * cosio2 + ps(395.0f) * cosio4)
               + temp3 * (ps(3.0f) + ps(-36.0f) * cosio2 + ps(49.0f) * cosio4);
    pf xhdot1 = pneg(temp1 * cosio);
    pf nodedot = xhdot1 + (ps(0.5f) * temp2 * (ps(4.0f) + ps(-19.0f) * cosio2)
               + ps(2.0f) * temp3 * (ps(3.0f) + ps(-7.0f) * cosio2)) * cosio;

    pf mo    = pk(pa[5], pb[5]);
    pf xmdf  = pfma(mdot, t, mo);
    pf argpm = pfma(argpdot, t, pk(pa[4], pb[4]));
    pf nodem = pfma(nodedot, t, pk(pa[3], pb[3]));

    pf cosargpo = pcos(pk(pa[4], pb[4]));
    pf cc3 = pdiv(ps(-2.0f * J3OJ2_F) * coef * tsi * no_unk * sinio, ecco);
    pf sinmao, cosmo;
    psc(mo, sinmao, cosmo);
    pf s_x, c_x;
    psc(xmdf, s_x, c_x);
    pf dmo = pfma(eta, cosmo, ps(1.0f));
    pf cx  = pfma(eta, c_x, ps(1.0f));
    pf per = bstar * cc3 * cosargpo * t
           + pdiv(ps(-X2O3_F) * coef * bstar, eeta)
             * (cx * cx * cx - dmo * dmo * dmo);
    pf mm = xmdf + per;
    argpm = argpm - per;
    pf sin_mm = pfma(c_x, per, s_x);

    pf cos2argpo = pfma(ps(2.0f) * cosargpo, cosargpo, ps(-1.0f));
    pf cc4 = ps(2.0f) * no_unk * coef1 * ao * omeosq * (
          eta * (ps(2.0f) + ps(0.5f) * etasq) + ecco * (ps(0.5f) + ps(2.0f) * etasq)
        - (jtsips * rao) * (ps(-3.0f) * con41 *
              (ps(1.0f) - ps(2.0f) * eeta + etasq * (ps(1.5f) - ps(0.5f) * eeta))
            + ps(0.75f) * x1mth2 * (ps(2.0f) * etasq - eeta * (ps(1.0f) + etasq)) * cos2argpo));
    pf cc5 = ps(2.0f) * coef1 * ao * omeosq * (ps(1.0f) + ps(2.75f) * (etasq + eeta) + eeta * etasq);
    pf em = ecco - (bstar * cc4 * t + bstar * cc5 * (sin_mm - sinmao));

    pf tempa = ps(1.0f) - cc1 * t;
    pf templ = ps(1.5f) * cc1 * t2;

    pf am = ao * tempa * tempa;
    pf rsam = prsqrt(am);
    pf sqam = am * rsam;
    pf nm = ps(XKE_F) * (rsam * rsam * rsam);
    mm = pfma(no_unk, templ, mm);
    pf xlm = pmod2pi(mm + argpm + nodem);

    pf sargpm, cargpm;
    psc(argpm, sargpm, cargpm);
    pf axnl = em * cargpm;
    pf tinv = prcp(am * (ps(1.0f) - em * em));
    pf aycof = ps(-0.5f * J3OJ2_F) * sinio;
    pf xlcof = pdiv(ps(-0.25f * J3OJ2_F) * sinio * pfma(ps(5.0f), cosio, ps(3.0f)), denom);
    pf aynl = pfma(tinv, aycof, em * sargpm);
    pf u = (xlm - nodem) + tinv * xlcof * axnl;

    // Kepler: one sincos + 2 analytic Newton steps, one rcp
    pf s_u, c_u;
    psc(u, s_u, c_u);
    pf num0 = axnl * s_u - aynl * c_u;
    pf rden = prcp(ps(1.0f) - axnl * c_u - aynl * s_u);
    pf dd1 = num0 * rden;
    pf dd1sq = dd1 * dd1;
    pf sind = dd1 * (ps(1.0f) - dd1sq * ps(1.0f / 6.0f));
    pf cosd = ps(1.0f) - ps(0.5f) * dd1sq + ps(1.0f / 24.0f) * (dd1sq * dd1sq);
    pf sE1 = pfma(s_u, cosd, c_u * sind);
    pf cE1 = c_u * cosd - s_u * sind;
    pf num1 = (axnl * sE1 - aynl * cE1) - dd1;
    pf dd2 = num1 * rden;
    pf sineo1 = pfma(cE1, dd2, sE1);
    pf coseo1 = cE1 - sE1 * dd2;

    pf ecose = pfma(axnl, coseo1, aynl * sineo1);
    pf esine = axnl * sineo1 - aynl * coseo1;
    pf el2 = pfma(axnl, axnl, aynl * aynl);
    pf pl = am * (ps(1.0f) - el2);
    pf rl = am * (ps(1.0f) - ecose);
    pf rlinv = prcp(rl);
    pf betal  = psqrt(ps(1.0f) - el2);
    pf rdotl  = sqam * esine * rlinv;
    pf rvdotl = sqam * betal * rlinv;
    pf tq = pdiv(esine, ps(1.0f) + betal);
    pf amorl = am * rlinv;
    pf sn = amorl * ((sineo1 - aynl) - axnl * tq);
    pf cn = amorl * ((coseo1 - axnl) + aynl * tq);
    pf sin2u = ps(2.0f) * cn * sn;
    pf cos2u = ps(1.0f) - ps(2.0f) * sn * sn;
    pf pli = prcp(pl);
    pf tb = ps(0.5f * J2_F) * pli;
    pf tc = tb * pli;

    pf mrt = rl * (ps(1.0f) - ps(1.5f) * tc * betal * con41) + ps(0.5f) * tb * x1mth2 * cos2u;
    pf x7thm1 = pfma(ps(7.0f), cosio2, ps(-1.0f));
    pf corr = ps(0.25f) * tc * x7thm1 * sin2u;
    pf ccor = ps(1.0f) - ps(0.5f) * corr * corr;
    pf sinsu = sn * ccor - cn * corr;
    pf cossu = pfma(sn, corr, cn * ccor);

    pf xnode = pfma(ps(1.5f) * tc * cosio, sin2u, nodem);
    pf mvt   = rdotl - nm * tb * x1mth2 * sin2u * ps(XKEI_F);
    pf rvdot = rvdotl + nm * tb * pfma(x1mth2, cos2u, ps(1.5f) * con41) * ps(XKEI_F);

    pf snod, cnod; psc(xnode, snod, cnod);
    pf di = ps(1.5f) * tc * cosio * sinio * cos2u;
    pf cdi = ps(1.0f) - ps(0.5f) * di * di;
    pf sini = pfma(cosio, di, sinio * cdi);
    pf cosi = cosio * cdi - sinio * di;

    pf xmx = pneg(snod) * cosi;
    pf xmy = cnod * cosi;
    pf ux = pfma(xmx, sinsu, cnod * cossu);
    pf uy = pfma(xmy, sinsu, snod * cossu);
    pf uz = sini * sinsu;
    pf vx = xmx * cossu - cnod * sinsu;
    pf vy = xmy * cossu - snod * sinsu;
    pf vz = sini * cossu;

    pf mr = mrt * ps(RE_F);
    PX = mr * ux;
    PY = mr * uy;
    PZ = mr * uz;
    VX = ps(VKPS_F) * pfma(mvt, ux, rvdot * vx);
    VY = ps(VKPS_F) * pfma(mvt, uy, rvdot * vy);
    VZ = ps(VKPS_F) * pfma(mvt, uz, rvdot * vz);
}

// 4 satellites per thread: two independent packed chains for ILP.
__global__ void __launch_bounds__(256)
sgp4_kernel(const float* __restrict__ P,   // (N,7)
            const float* __restrict__ T,   // (N,)
            float* __restrict__ out,       // pos(3N) then vel(3N)
            int N)
{
    int iq = blockIdx.x * blockDim.x + threadIdx.x;   // quad index
    int s0 = 4 * iq;
    if (s0 >= N) return;
    bool full = (s0 + 3 < N);

    float a[28];
    float tv[4];
    if (full) {
        const float4* q = reinterpret_cast<const float4*>(P + 28 * (size_t)iq);
#pragma unroll
        for (int k = 0; k < 7; k++) {
            float4 w = q[k];
            a[4 * k + 0] = w.x; a[4 * k + 1] = w.y;
            a[4 * k + 2] = w.z; a[4 * k + 3] = w.w;
        }
        float4 tt = *reinterpret_cast<const float4*>(T + 4 * (size_t)iq);
        tv[0] = tt.x; tv[1] = tt.y; tv[2] = tt.z; tv[3] = tt.w;
    } else {
#pragma unroll
        for (int j = 0; j < 4; j++) {
            int idx = s0 + j; if (idx > N - 1) idx = N - 1;
#pragma unroll
            for (int k = 0; k < 7; k++) a[7 * j + k] = P[7 * (size_t)idx + k];
            tv[j] = T[idx];
        }
    }

    pf PX0, PY0, PZ0, VX0, VY0, VZ0;
    pf PX1, PY1, PZ1, VX1, VY1, VZ1;
    sgp4_core(a + 0,  a + 7,  tv[0], tv[1], PX0, PY0, PZ0, VX0, VY0, VZ0);
    sgp4_core(a + 14, a + 21, tv[2], tv[3], PX1, PY1, PZ1, VX1, VY1, VZ1);

    float2 px0 = up(PX0), py0 = up(PY0), pz0 = up(PZ0);
    float2 vx0 = up(VX0), vy0 = up(VY0), vz0 = up(VZ0);
    float2 px1 = up(PX1), py1 = up(PY1), pz1 = up(PZ1);
    float2 vx1 = up(VX1), vy1 = up(VY1), vz1 = up(VZ1);

    float* pos = out;
    float* vel = out + 3 * (size_t)N;
    size_t base = 12 * (size_t)iq;
    if (full) {
        float4* pp = reinterpret_cast<float4*>(pos + base);
        pp[0] = make_float4(px0.x, py0.x, pz0.x, px0.y);
        pp[1] = make_float4(py0.y, pz0.y, px1.x, py1.x);
        pp[2] = make_float4(pz1.x, px1.y, py1.y, pz1.y);
        float4* vv = reinterpret_cast<float4*>(vel + base);
        vv[0] = make_float4(vx0.x, vy0.x, vz0.x, vx0.y);
        vv[1] = make_float4(vy0.y, vz0.y, vx1.x, vy1.x);
        vv[2] = make_float4(vz1.x, vx1.y, vy1.y, vz1.y);
    } else {
        float pxs[4] = {px0.x, px0.y, px1.x, px1.y};
        float pys[4] = {py0.x, py0.y, py1.x, py1.y};
        float pzs[4] = {pz0.x, pz0.y, pz1.x, pz1.y};
        float vxs[4] = {vx0.x, vx0.y, vx1.x, vx1.y};
        float vys[4] = {vy0.x, vy0.y, vy1.x, vy1.y};
        float vzs[4] = {vz0.x, vz0.y, vz1.x, vz1.y};
#pragma unroll
        for (int j = 0; j < 4; j++) {
            if (s0 + j < N) {
                pos[base + 3 * j + 0] = pxs[j];
                pos[base + 3 * j + 1] = pys[j];
                pos[base + 3 * j + 2] = pzs[j];
                vel[base + 3 * j + 0] = vxs[j];
                vel[base + 3 * j + 1] = vys[j];
                vel[base + 3 * j + 2] = vzs[j];
            }
        }
    }
}

extern "C" void kernel_launch(void* const* d_in, const int* in_sizes, int n_in,
                              void* d_out, int out_size) {
    const float* params = (const float*)d_in[0];   // (N,7) float32
    const float* tmin   = (const float*)d_in[1];   // (N,)  float32
    float* out = (float*)d_out;                    // pos(3N) | vel(3N)
    int N = in_sizes[1];
    int quads = (N + 3) / 4;
    int threads = 256;
    int blocks = (quads + threads - 1) / threads;
    sgp4_kernel<<<blocks, threads>>>(params, tmin, out, N);
}

// round 13
// speedup vs baseline: 1.1789x; 1.1789x over previous
#include <cuda_runtime.h>
#include <math.h>

#define RE_D   6378.137
#define MU_D   398600.5
#define TWOPI_F 6.28318530717958647692f
#define INV_TWOPI_F 0.15915494309189533577f

#define XKE_F   ((float)(60.0 / sqrt(RE_D * RE_D * RE_D / MU_D)))
#define XKEI_F  ((float)(sqrt(RE_D * RE_D * RE_D / MU_D) / 60.0))
#define RE_F    ((float)RE_D)
#define J2_F    0.00108262998905f
#define J4_F    (-0.00000161098761f)
#define J3OJ2_F ((float)(-0.00000253215306 / 0.00108262998905))
#define X2O3_F  ((float)(2.0 / 3.0))
#define SS_F    ((float)(78.0 / RE_D + 1.0))
#define QZMS2T_F ((float)(((120.0 - 78.0) / RE_D) * ((120.0 - 78.0) / RE_D) \
                        * ((120.0 - 78.0) / RE_D) * ((120.0 - 78.0) / RE_D)))
#define VKPS_F  ((float)(RE_D * (60.0 / sqrt(RE_D * RE_D * RE_D / MU_D)) / 60.0))

// ---------------- packed f32x2: 2 satellites per thread ----------------
struct pf { unsigned long long v; };

__device__ __forceinline__ pf pk(float x, float y) {
    pf r; asm("mov.b64 %0,{%1,%2};" : "=l"(r.v) : "f"(x), "f"(y)); return r;
}
__device__ __forceinline__ float2 up(pf a) {
    float2 r; asm("mov.b64 {%0,%1},%2;" : "=f"(r.x), "=f"(r.y) : "l"(a.v)); return r;
}
__device__ __forceinline__ pf ps(float s) { return pk(s, s); }

__device__ __forceinline__ pf operator+(pf a, pf b) {
    pf r; asm("add.rn.f32x2 %0,%1,%2;" : "=l"(r.v) : "l"(a.v), "l"(b.v)); return r;
}
__device__ __forceinline__ pf operator*(pf a, pf b) {
    pf r; asm("mul.rn.f32x2 %0,%1,%2;" : "=l"(r.v) : "l"(a.v), "l"(b.v)); return r;
}
__device__ __forceinline__ pf pfma(pf a, pf b, pf c) {
    pf r; asm("fma.rn.f32x2 %0,%1,%2,%3;" : "=l"(r.v) : "l"(a.v), "l"(b.v), "l"(c.v)); return r;
}
__device__ __forceinline__ pf operator-(pf a, pf b) { return pfma(b, ps(-1.0f), a); }
__device__ __forceinline__ pf pneg(pf a) { return a * ps(-1.0f); }

// ---- scalar-per-half helpers (MUFU / floor not packable) ----
__device__ __forceinline__ float frcp(float x) { float r; asm("rcp.approx.f32 %0,%1;" : "=f"(r) : "f"(x)); return r; }
__device__ __forceinline__ float fsqa(float x) { float r; asm("sqrt.approx.f32 %0,%1;" : "=f"(r) : "f"(x)); return r; }
__device__ __forceinline__ float frsq(float x) { float r; asm("rsqrt.approx.f32 %0,%1;" : "=f"(r) : "f"(x)); return r; }

__device__ __forceinline__ pf prcp(pf a)  { float2 t = up(a); return pk(frcp(t.x), frcp(t.y)); }
__device__ __forceinline__ pf pdiv(pf a, pf b) { return a * prcp(b); }
__device__ __forceinline__ pf psqrt(pf a) { float2 t = up(a); return pk(fsqa(t.x), fsqa(t.y)); }
__device__ __forceinline__ pf prsqrt(pf a){ float2 t = up(a); return pk(frsq(t.x), frsq(t.y)); }
__device__ __forceinline__ pf pfloor(pf a){ float2 t = up(a); return pk(floorf(t.x), floorf(t.y)); }
__device__ __forceinline__ pf pcos(pf a)  { float2 t = up(a); return pk(__cosf(t.x), __cosf(t.y)); }
__device__ __forceinline__ void psc(pf a, pf& s, pf& c) {
    float2 t = up(a); float s0, c0, s1, c1;
    __sincosf(t.x, &s0, &c0); __sincosf(t.y, &s1, &c1);
    s = pk(s0, s1); c = pk(c0, c1);
}
__device__ __forceinline__ pf pmod2pi(pf x) {
    pf q = pfloor(x * ps(INV_TWOPI_F));
    return pfma(q, ps(-TWOPI_F), x);
}

// Inclination trig: hybrid fast/Taylor. The 1+cosio cancellation (divided
// into xlcof) needs effectively-correctly-rounded cos only near pi. There,
// delta = pi - inclo is tiny; Cody-Waite delta (Sterbenz-exact subtraction
// from PI_HI, then +PI_LO) + Taylor gives cos/sin with ~4e-15 error at the
// rounding knife-edge — matching the libm behavior validated in R3-R11,
// without the ~100-instr Payne-Hanek inline blob.
#define PI_HI_F 3.14159274101257324219f   // f32(pi)
#define PI_LO_F (-8.74227765734758577e-8f) // pi - f32(pi)
__device__ __forceinline__ void incl_trig(float inclo, float& s, float& c, float& d) {
    if (inclo > 3.1296f) {
        float dl = (PI_HI_F - inclo) + PI_LO_F;   // delta in [ -8.7e-8, 0.012 ]
        float d2s = dl * dl;
        s = dl * (1.0f - d2s * (1.0f / 6.0f) * (1.0f - d2s * 0.05f));  // sin(dl), 5th order
        float cd = 1.0f - 0.5f * d2s * (1.0f - d2s * (1.0f / 12.0f) * (1.0f - d2s * (1.0f / 30.0f)));
        c = -cd;                                   // cos(inclo) = -cos(dl)
        float dd = 1.0f + c;
        d = (fabsf(dd) > 1.5e-12f) ? dd : 1.5e-12f;
    } else {
        __sincosf(inclo, &s, &c);
        d = 1.0f + c;
    }
}

// Specialization (R6/R9): input support -> isimp=false, sfour=SS,
// qzms24=QZMS2T, ecco>1e-4, eeta>3e-6; cc1<=2.9e-11 kills d2..d4,
// t3cof..t5cof, nodecf below f32 rounding; |per|<=6.5e-5; em>0 (clamp dead).

__global__ void __launch_bounds__(256)
sgp4_kernel(const float* __restrict__ P,   // (N,7)
            const float* __restrict__ T,   // (N,)
            float* __restrict__ out,       // pos(3N) then vel(3N)
            int N)
{
    int ip = blockIdx.x * blockDim.x + threadIdx.x;   // pair index
    int s0 = 2 * ip;
    if (s0 >= N) return;
    bool has2 = (s0 + 1 < N);

    // -------- loads --------
    float a[14];
    float t0v, t1v;
    if (has2) {
        const float2* q = reinterpret_cast<const float2*>(P + 14 * (size_t)ip);
#pragma unroll
        for (int k = 0; k < 7; k++) { float2 w = q[k]; a[2 * k] = w.x; a[2 * k + 1] = w.y; }
        float2 tt = *reinterpret_cast<const float2*>(T + 2 * (size_t)ip);
        t0v = tt.x; t1v = tt.y;
    } else {
#pragma unroll
        for (int k = 0; k < 7; k++) { a[k] = P[7 * (size_t)s0 + k]; }
#pragma unroll
        for (int k = 0; k < 7; k++) { a[7 + k] = a[k]; }
        t0v = T[s0]; t1v = t0v;
    }

    pf ecco  = pk(a[1], a[8]);
    pf inclo = pk(a[2], a[9]);
    pf bstar = pk(a[6], a[13]);
    pf t     = pk(t0v, t1v);
    pf t2 = t * t;

    // ---------------- core orbit constants ----------------
    pf omeosq = ps(1.0f) - ecco * ecco;
    pf rteosq = psqrt(omeosq);

    float si0, ci0, dn0, si1, ci1, dn1;
    incl_trig(a[2], si0, ci0, dn0);
    incl_trig(a[9], si1, ci1, dn1);
    pf sinio = pk(si0, si1);
    pf cosio = pk(ci0, ci1);
    pf denom = pk(dn0, dn1);
    pf cosio2 = cosio * cosio;

    float ak0 = __powf(__fdividef(XKE_F, a[0]), X2O3_F);
    float ak1 = __powf(__fdividef(XKE_F, a[7]), X2O3_F);
    pf ak = pk(ak0, ak1);
    pf n_koz = pk(a[0], a[7]);

    pf d1   = pdiv(ps(0.75f * J2_F) * pfma(ps(3.0f), cosio2, ps(-1.0f)), rteosq * omeosq);
    pf del1 = pdiv(d1, ak * ak);
    pf dl1sq = del1 * del1;
    // 134/81*del1^3 term <=5e-9 < ulp(1): dropped
    pf adel = ak * (ps(1.0f) - dl1sq - del1 * ps(1.0f / 3.0f));
    pf del_ = pdiv(d1, adel * adel);
    pf dsq = del_ * del_;
    pf no_unk = pdiv(n_koz, ps(1.0f) + del_);
    // (4/81)*del^3 term <=1.7e-10 < ulp(1): dropped
    pf ao = ak * (ps(1.0f) + ps(X2O3_F) * del_ + ps(-1.0f / 9.0f) * dsq);

    pf po    = ao * omeosq;
    pf con42 = pfma(ps(-5.0f), cosio2, ps(1.0f));
    pf con41 = pfma(ps(-2.0f), cosio2, pneg(con42));
    pf pinvsq = prcp(po * po);
    pf tsi    = prcp(ao - ps(SS_F));
    pf eta    = ao * ecco * tsi;
    pf etasq  = eta * eta;
    pf eeta   = ecco * eta;
    pf psisq  = ps(1.0f) - etasq;          // etasq<=0.04 -> positive
    pf rs     = prsqrt(psisq);
    pf rpsi   = rs * rs;                   // 1/psisq (one MUFU serves both)
    pf rao    = prcp(ao);
    pf tsi2   = tsi * tsi;
    pf coef   = ps(QZMS2T_F) * (tsi2 * tsi2);
    pf coef1  = coef * (rpsi * rpsi) * (rpsi * rs);   // coef/psisq^3.5
    pf x1mth2 = ps(1.0f) - cosio2;
    pf cosio4 = cosio2 * cosio2;

    pf jtsips = ps(J2_F) * tsi * rpsi;
    pf cc2 = coef1 * no_unk * (ao * (ps(1.0f) + ps(1.5f) * etasq + eeta * (ps(4.0f) + etasq))
           + ps(0.375f) * jtsips * con41 * (ps(8.0f) + ps(3.0f) * etasq * (ps(8.0f) + etasq)));
    pf cc1 = bstar * cc2;

    // ---- secular rates -> epoch angles at time t ----
    pf temp1 = ps(1.5f * J2_F) * pinvsq * no_unk;
    pf temp2 = ps(0.5f) * temp1 * ps(J2_F) * pinvsq;
    pf temp3 = ps(-0.46875f * J4_F) * pinvsq * pinvsq * no_unk;
    pf mdot = no_unk + ps(0.5f) * temp1 * rteosq * con41
            + ps(0.0625f) * temp2 * rteosq *
              (ps(13.0f) + ps(-78.0f) * cosio2 + ps(137.0f) * cosio4);
    pf argpdot = ps(-0.5f) * temp1 * con42
               + ps(0.0625f) * temp2 * (ps(7.0f) + ps(-114.0f) * cosio2 + ps(395.0f) * cosio4)
               + temp3 * (ps(3.0f) + ps(-36.0f) * cosio2 + ps(49.0f) * cosio4);
    pf xhdot1 = pneg(temp1 * cosio);
    pf nodedot = xhdot1 + (ps(0.5f) * temp2 * (ps(4.0f) + ps(-19.0f) * cosio2)
               + ps(2.0f) * temp3 * (ps(3.0f) + ps(-7.0f) * cosio2)) * cosio;

    pf mo    = pk(a[5], a[12]);
    pf xmdf  = pfma(mdot, t, mo);
    pf argpm = pfma(argpdot, t, pk(a[4], a[11]));
    pf nodem = pfma(nodedot, t, pk(a[3], a[10]));  // range safe, mod unneeded

    // ---- periodic drag terms (|per| <= 6.5e-5) ----
    pf cosargpo = pcos(pk(a[4], a[11]));
    pf cc3 = pdiv(ps(-2.0f * J3OJ2_F) * coef * tsi * no_unk * sinio, ecco);
    pf sinmao, cosmo;
    psc(mo, sinmao, cosmo);
    pf s_x, c_x;
    psc(xmdf, s_x, c_x);
    pf dmo = pfma(eta, cosmo, ps(1.0f));
    pf cx  = pfma(eta, c_x, ps(1.0f));
    pf per = bstar * cc3 * cosargpo * t
           + pdiv(ps(-X2O3_F) * coef * bstar, eeta)
             * (cx * cx * cx - dmo * dmo * dmo);
    pf mm = xmdf + per;
    argpm = argpm - per;
    pf sin_mm = pfma(c_x, per, s_x);    // sin(xmdf+per), 1st order (err ~2e-9)

    // ---- tempe ----
    pf cos2argpo = pfma(ps(2.0f) * cosargpo, cosargpo, ps(-1.0f));
    pf cc4 = ps(2.0f) * no_unk * coef1 * ao * omeosq * (
          eta * (ps(2.0f) + ps(0.5f) * etasq) + ecco * (ps(0.5f) + ps(2.0f) * etasq)
        - (jtsips * rao) * (ps(-3.0f) * con41 *
              (ps(1.0f) - ps(2.0f) * eeta + etasq * (ps(1.5f) - ps(0.5f) * eeta))
            + ps(0.75f) * x1mth2 * (ps(2.0f) * etasq - eeta * (ps(1.0f) + etasq)) * cos2argpo));
    pf cc5 = ps(2.0f) * coef1 * ao * omeosq * (ps(1.0f) + ps(2.75f) * (etasq + eeta) + eeta * etasq);
    pf em = ecco - (bstar * cc4 * t + bstar * cc5 * (sin_mm - sinmao));

    // ---- tempa / templ: higher drag coeffs provably sub-ulp, dropped ----
    pf tempa = ps(1.0f) - cc1 * t;
    pf templ = ps(1.5f) * cc1 * t2;

    pf am = ao * tempa * tempa;
    pf rsam = prsqrt(am);
    pf sqam = am * rsam;
    pf nm = ps(XKE_F) * (rsam * rsam * rsam);
    mm = pfma(no_unk, templ, mm);
    pf xlm = pmod2pi(mm + argpm + nodem);

    pf sargpm, cargpm;
    psc(argpm, sargpm, cargpm);
    pf axnl = em * cargpm;
    pf tinv = prcp(am * (ps(1.0f) - em * em));
    pf aycof = ps(-0.5f * J3OJ2_F) * sinio;
    pf xlcof = pdiv(ps(-0.25f * J3OJ2_F) * sinio * pfma(ps(5.0f), cosio, ps(3.0f)), denom);
    pf aynl = pfma(tinv, aycof, em * sargpm);
    pf u = (xlm - nodem) + tinv * xlcof * axnl;

    // ---- Kepler: one sincos + 2 analytic Newton steps, one rcp ----
    pf s_u, c_u;
    psc(u, s_u, c_u);
    pf num0 = axnl * s_u - aynl * c_u;
    pf rden = prcp(ps(1.0f) - axnl * c_u - aynl * s_u);
    pf dd1 = num0 * rden;
    pf dd1sq = dd1 * dd1;
    pf sind = dd1 * (ps(1.0f) - dd1sq * ps(1.0f / 6.0f));
    pf cosd = ps(1.0f) - ps(0.5f) * dd1sq + ps(1.0f / 24.0f) * (dd1sq * dd1sq);
    pf sE1 = pfma(s_u, cosd, c_u * sind);
    pf cE1 = c_u * cosd - s_u * sind;
    pf num1 = (axnl * sE1 - aynl * cE1) - dd1;
    pf dd2 = num1 * rden;
    pf sineo1 = pfma(cE1, dd2, sE1);
    pf coseo1 = cE1 - sE1 * dd2;

    pf ecose = pfma(axnl, coseo1, aynl * sineo1);
    pf esine = axnl * sineo1 - aynl * coseo1;
    pf el2 = pfma(axnl, axnl, aynl * aynl);
    pf pl = am * (ps(1.0f) - el2);
    pf rl = am * (ps(1.0f) - ecose);
    pf rlinv = prcp(rl);
    pf betal  = psqrt(ps(1.0f) - el2);
    pf rdotl  = sqam * esine * rlinv;
    pf rvdotl = sqam * betal * rlinv;
    pf tq = pdiv(esine, ps(1.0f) + betal);
    pf amorl = am * rlinv;
    pf sn = amorl * ((sineo1 - aynl) - axnl * tq);
    pf cn = amorl * ((coseo1 - axnl) + aynl * tq);
    pf sin2u = ps(2.0f) * cn * sn;
    pf cos2u = ps(1.0f) - ps(2.0f) * sn * sn;
    pf pli = prcp(pl);
    pf tb = ps(0.5f * J2_F) * pli;
    pf tc = tb * pli;

    pf mrt = rl * (ps(1.0f) - ps(1.5f) * tc * betal * con41) + ps(0.5f) * tb * x1mth2 * cos2u;
    pf x7thm1 = pfma(ps(7.0f), cosio2, ps(-1.0f));
    pf corr = ps(0.25f) * tc * x7thm1 * sin2u;
    pf ccor = ps(1.0f) - ps(0.5f) * corr * corr;
    pf sinsu = sn * ccor - cn * corr;
    pf cossu = pfma(sn, corr, cn * ccor);

    pf xnode = pfma(ps(1.5f) * tc * cosio, sin2u, nodem);
    pf mvt   = rdotl - nm * tb * x1mth2 * sin2u * ps(XKEI_F);
    pf rvdot = rvdotl + nm * tb * pfma(x1mth2, cos2u, ps(1.5f) * con41) * ps(XKEI_F);

    pf snod, cnod; psc(xnode, snod, cnod);
    pf di = ps(1.5f) * tc * cosio * sinio * cos2u;
    pf cdi = ps(1.0f) - ps(0.5f) * di * di;
    pf sini = pfma(cosio, di, sinio * cdi);
    pf cosi = cosio * cdi - sinio * di;

    pf xmx = pneg(snod) * cosi;
    pf xmy = cnod * cosi;
    pf ux = pfma(xmx, sinsu, cnod * cossu);
    pf uy = pfma(xmy, sinsu, snod * cossu);
    pf uz = sini * sinsu;
    pf vx = xmx * cossu - cnod * sinsu;
    pf vy = xmy * cossu - snod * sinsu;
    pf vz = sini * cossu;

    pf mr = mrt * ps(RE_F);
    pf PX = mr * ux;
    pf PY = mr * uy;
    pf PZ = mr * uz;
    pf VX = ps(VKPS_F) * pfma(mvt, ux, rvdot * vx);
    pf VY = ps(VKPS_F) * pfma(mvt, uy, rvdot * vy);
    pf VZ = ps(VKPS_F) * pfma(mvt, uz, rvdot * vz);

    float2 px = up(PX), py = up(PY), pz = up(PZ);
    float2 vxx = up(VX), vyy = up(VY), vzz = up(VZ);

    float* pos = out;
    float* vel = out + 3 * (size_t)N;
    size_t base = 6 * (size_t)ip;
    if (has2) {
        *reinterpret_cast<float2*>(pos + base + 0) = make_float2(px.x, py.x);
        *reinterpret_cast<float2*>(pos + base + 2) = make_float2(pz.x, px.y);
        *reinterpret_cast<float2*>(pos + base + 4) = make_float2(py.y, pz.y);
        *reinterpret_cast<float2*>(vel + base + 0) = make_float2(vxx.x, vyy.x);
        *reinterpret_cast<float2*>(vel + base + 2) = make_float2(vzz.x, vxx.y);
        *reinterpret_cast<float2*>(vel + base + 4) = make_float2(vyy.y, vzz.y);
    } else {
        pos[base + 0] = px.x; pos[base + 1] = py.x; pos[base + 2] = pz.x;
        vel[base + 0] = vxx.x; vel[base + 1] = vyy.x; vel[base + 2] = vzz.x;
    }
}

extern "C" void kernel_launch(void* const* d_in, const int* in_sizes, int n_in,
                              void* d_out, int out_size) {
    const float* params = (const float*)d_in[0];   // (N,7) float32
    const float* tmin   = (const float*)d_in[1];   // (N,)  float32
    float* out = (float*)d_out;                    // pos(3N) | vel(3N)
    int N = in_sizes[1];
    int pairs = (N + 1) / 2;
    int threads = 256;
    int blocks = (pairs + threads - 1) / threads;
    sgp4_kernel<<<blocks, threads>>>(params, tmin, out, N);
}